// round 8
// baseline (speedup 1.0000x reference)
#include <cuda_runtime.h>
#include <cuda_fp16.h>
#include <cstdint>

#define BATCH   4096
#define IN_DIM  4096
#define OUT_DIM 4096
#define BN_EPS  1e-3f

#define XS_STRIDE 72   // halves; 144B row stride -> ldmatrix conflict-free
#define BS_STRIDE 72   // halves

// SMEM: Xs[128][72] half | Bs[64][72] half | bias_s[64] f32
#define XS_OFF   0
#define BS_OFF   (128 * XS_STRIDE * 2)          // 18432
#define BIAS_OFF (BS_OFF + 64 * BS_STRIDE * 2)  // 27648
#define SMEM_TOTAL (BIAS_OFF + 64 * 4)          // 27904

// ---------------- scratch ---------------------------------------------------
__device__ float g_sum[OUT_DIM];
__device__ float g_sumsq[OUT_DIM];
__device__ float g_scale[OUT_DIM];
__device__ float g_shift[OUT_DIM];
__device__ uint4 g_mid4[BATCH * OUT_DIM / 8];   // fp16 pre-BN intermediate (33MB)

__device__ __forceinline__ uint32_t smem_u32(const void* p) {
    uint32_t a;
    asm("{ .reg .u64 t; cvta.to.shared.u64 t, %1; cvt.u32.u64 %0, t; }" : "=r"(a) : "l"(p));
    return a;
}
__device__ __forceinline__ void ldsm_x4(uint32_t a[4], uint32_t addr) {
    asm volatile("ldmatrix.sync.aligned.m8n8.x4.shared.b16 {%0,%1,%2,%3}, [%4];"
                 : "=r"(a[0]), "=r"(a[1]), "=r"(a[2]), "=r"(a[3]) : "r"(addr));
}
__device__ __forceinline__ void ldsm_x4_t(uint32_t a[4], uint32_t addr) {
    asm volatile("ldmatrix.sync.aligned.m8n8.x4.trans.shared.b16 {%0,%1,%2,%3}, [%4];"
                 : "=r"(a[0]), "=r"(a[1]), "=r"(a[2]), "=r"(a[3]) : "r"(addr));
}
__device__ __forceinline__ void mma_f16(float c[4], const uint32_t a[4],
                                        const uint32_t b0, const uint32_t b1) {
    asm volatile(
        "mma.sync.aligned.m16n8k16.row.col.f32.f16.f16.f32 "
        "{%0,%1,%2,%3}, {%4,%5,%6,%7}, {%8,%9}, {%0,%1,%2,%3};"
        : "+f"(c[0]), "+f"(c[1]), "+f"(c[2]), "+f"(c[3])
        : "r"(a[0]), "r"(a[1]), "r"(a[2]), "r"(a[3]), "r"(b0), "r"(b1));
}

// ---------------- kernels ---------------------------------------------------
__global__ void zero_stats_kernel() {
    int i = blockIdx.x * blockDim.x + threadIdx.x;
    if (i < OUT_DIM) { g_sum[i] = 0.f; g_sumsq[i] = 0.f; }
}

__global__ __launch_bounds__(128) void gemm_stats_kernel(
    const float* __restrict__ x, const float* __restrict__ w,
    const float* __restrict__ bias)
{
    extern __shared__ char smem[];
    __half* Xs = (__half*)(smem + XS_OFF);
    __half* Bs = (__half*)(smem + BS_OFF);
    float* bias_s = (float*)(smem + BIAS_OFF);
    const uint32_t smem_base = smem_u32(smem);

    const int tid  = threadIdx.x;
    const int wid  = tid >> 5;
    const int lane = tid & 31;
    const int gid  = lane >> 2;
    const int tig  = lane & 3;
    const int s       = blockIdx.y;
    const int rowBase = blockIdx.x * 128;

    // ---- X tile [128 x 64] f32 -> f16 SMEM ----
    #pragma unroll
    for (int i = 0; i < 16; i++) {
        int idx = i * 128 + tid;
        int row = idx >> 4;
        int c4  = idx & 15;
        float4 v = *(const float4*)(x + (size_t)(rowBase + row) * IN_DIM + s * 64 + c4 * 4);
        __half2 h0 = __floats2half2_rn(v.x, v.y);
        __half2 h1 = __floats2half2_rn(v.z, v.w);
        uint2 u = make_uint2(*(uint32_t*)&h0, *(uint32_t*)&h1);
        *(uint2*)(Xs + row * XS_STRIDE + c4 * 4) = u;
    }
    // ---- W block K-major: Bs[k][n] = w[s*64+k][s*64+n], f16 ----
    #pragma unroll
    for (int i = 0; i < 8; i++) {
        int idx = i * 128 + tid;
        int k  = idx >> 4;
        int c4 = idx & 15;
        float4 v = *(const float4*)(w + (size_t)(s * 64 + k) * OUT_DIM + s * 64 + c4 * 4);
        __half2 h0 = __floats2half2_rn(v.x, v.y);
        __half2 h1 = __floats2half2_rn(v.z, v.w);
        uint2 u = make_uint2(*(uint32_t*)&h0, *(uint32_t*)&h1);
        *(uint2*)(Bs + k * BS_STRIDE + c4 * 4) = u;
    }
    if (tid < 16) {
        float4 v = *(const float4*)(bias + s * 64 + tid * 4);
        *(float4*)(bias_s + tid * 4) = v;
    }
    __syncthreads();

    // ---- ldmatrix lane base addresses ----
    const int l8   = lane & 7;
    const int lh   = (lane >> 3) & 1;
    const int lq   = lane >> 4;
    uint32_t a_addr[2];
    #pragma unroll
    for (int mc = 0; mc < 2; mc++) {
        int r = wid * 32 + mc * 16 + l8 + lh * 8;
        a_addr[mc] = smem_base + XS_OFF + r * (XS_STRIDE * 2) + lq * 16;
    }
    const int krow = l8 + lh * 8;
    uint32_t b_addr = smem_base + BS_OFF + krow * (BS_STRIDE * 2) + lq * 16;

    // ---- fp16 tensor-core mainloop: K=64 in 4 steps of k16 ----
    float c[2][8][4];
    #pragma unroll
    for (int mc = 0; mc < 2; mc++)
        #pragma unroll
        for (int nc = 0; nc < 8; nc++)
            #pragma unroll
            for (int q = 0; q < 4; q++)
                c[mc][nc][q] = 0.f;

    #pragma unroll
    for (int kc = 0; kc < 4; kc++) {
        uint32_t a[2][4];
        ldsm_x4(a[0], a_addr[0] + kc * 32);
        ldsm_x4(a[1], a_addr[1] + kc * 32);
        uint32_t b[8][2];
        #pragma unroll
        for (int p = 0; p < 4; p++) {
            uint32_t t[4];
            ldsm_x4_t(t, b_addr + kc * 16 * (BS_STRIDE * 2) + p * 32);
            b[2 * p][0]     = t[0];
            b[2 * p][1]     = t[1];
            b[2 * p + 1][0] = t[2];
            b[2 * p + 1][1] = t[3];
        }
        #pragma unroll
        for (int mc = 0; mc < 2; mc++)
            #pragma unroll
            for (int nc = 0; nc < 8; nc++)
                mma_f16(c[mc][nc], a[mc], b[nc][0], b[nc][1]);
    }
    __syncthreads();   // done reading Xs/Bs; reuse Xs as fp16 stage

    // ---- epilogue: bias, shuffle stats, fp16 stage ----
    __half* stage = Xs;
    const int colBase = s * 64;
    #pragma unroll
    for (int nc = 0; nc < 8; nc++) {
        const int col = nc * 8 + 2 * tig;
        const float bx = bias_s[col], by = bias_s[col + 1];
        float v[2][4];
        #pragma unroll
        for (int mc = 0; mc < 2; mc++) {
            v[mc][0] = c[mc][nc][0] + bx;
            v[mc][1] = c[mc][nc][1] + by;
            v[mc][2] = c[mc][nc][2] + bx;
            v[mc][3] = c[mc][nc][3] + by;
        }
        float s0 = v[0][0] + v[0][2] + v[1][0] + v[1][2];
        float s1 = v[0][1] + v[0][3] + v[1][1] + v[1][3];
        float q0 = fmaf(v[0][0], v[0][0], fmaf(v[0][2], v[0][2],
                   fmaf(v[1][0], v[1][0], v[1][2] * v[1][2])));
        float q1 = fmaf(v[0][1], v[0][1], fmaf(v[0][3], v[0][3],
                   fmaf(v[1][1], v[1][1], v[1][3] * v[1][3])));
        #pragma unroll
        for (int m = 4; m < 32; m <<= 1) {
            s0 += __shfl_xor_sync(0xffffffffu, s0, m);
            s1 += __shfl_xor_sync(0xffffffffu, s1, m);
            q0 += __shfl_xor_sync(0xffffffffu, q0, m);
            q1 += __shfl_xor_sync(0xffffffffu, q1, m);
        }
        if (gid == 0) {
            atomicAdd(&g_sum[colBase + col],       s0);
            atomicAdd(&g_sum[colBase + col + 1],   s1);
            atomicAdd(&g_sumsq[colBase + col],     q0);
            atomicAdd(&g_sumsq[colBase + col + 1], q1);
        }
        #pragma unroll
        for (int mc = 0; mc < 2; mc++) {
            const int r = wid * 32 + mc * 16 + gid;
            __half2 h0 = __floats2half2_rn(v[mc][0], v[mc][1]);
            __half2 h1 = __floats2half2_rn(v[mc][2], v[mc][3]);
            *(__half2*)(stage + r * XS_STRIDE + col)       = h0;
            *(__half2*)(stage + (r + 8) * XS_STRIDE + col) = h1;
        }
    }
    __syncthreads();

    // ---- coalesced 16B stores of fp16 tile to g_mid ----
    #pragma unroll
    for (int i = 0; i < 8; i++) {
        int idx = i * 128 + tid;   // 0..1023
        int row = idx >> 3;
        int q   = idx & 7;
        uint4 u = *(uint4*)(stage + row * XS_STRIDE + q * 8);
        g_mid4[(size_t)(rowBase + row) * (OUT_DIM / 8) + s * 8 + q] = u;
    }
}

__global__ void finalize_kernel(const float* __restrict__ gamma,
                                const float* __restrict__ beta) {
    int j = blockIdx.x * blockDim.x + threadIdx.x;
    if (j < OUT_DIM) {
        const float invB = 1.0f / (float)BATCH;
        float mean = g_sum[j] * invB;
        float var  = fmaxf(g_sumsq[j] * invB - mean * mean, 0.f);
        float sc   = gamma[j] * rsqrtf(var + BN_EPS);
        g_scale[j] = sc;
        g_shift[j] = fmaf(-mean, sc, beta[j]);
    }
}

__global__ __launch_bounds__(256) void pass2_kernel(float* __restrict__ out) {
    int base = blockIdx.x * 512 + threadIdx.x;
    #pragma unroll
    for (int t = 0; t < 2; t++) {
        int idx = base + t * 256;            // uint4 (8 halves) index
        int colb = (idx & (OUT_DIM / 8 - 1)) * 8;
        uint4 u = g_mid4[idx];
        float2 f0 = __half22float2(*(__half2*)&u.x);
        float2 f1 = __half22float2(*(__half2*)&u.y);
        float2 f2 = __half22float2(*(__half2*)&u.z);
        float2 f3 = __half22float2(*(__half2*)&u.w);
        float4 sc0 = *(const float4*)(g_scale + colb);
        float4 sc1 = *(const float4*)(g_scale + colb + 4);
        float4 sh0 = *(const float4*)(g_shift + colb);
        float4 sh1 = *(const float4*)(g_shift + colb + 4);
        float4 o0, o1;
        o0.x = fmaxf(fmaf(f0.x, sc0.x, sh0.x), 0.f);
        o0.y = fmaxf(fmaf(f0.y, sc0.y, sh0.y), 0.f);
        o0.z = fmaxf(fmaf(f1.x, sc0.z, sh0.z), 0.f);
        o0.w = fmaxf(fmaf(f1.y, sc0.w, sh0.w), 0.f);
        o1.x = fmaxf(fmaf(f2.x, sc1.x, sh1.x), 0.f);
        o1.y = fmaxf(fmaf(f2.y, sc1.y, sh1.y), 0.f);
        o1.z = fmaxf(fmaf(f3.x, sc1.z, sh1.z), 0.f);
        o1.w = fmaxf(fmaf(f3.y, sc1.w, sh1.w), 0.f);
        ((float4*)out)[idx * 2]     = o0;
        ((float4*)out)[idx * 2 + 1] = o1;
    }
}

extern "C" void kernel_launch(void* const* d_in, const int* in_sizes, int n_in,
                              void* d_out, int out_size) {
    const float* x     = (const float*)d_in[0];
    const float* w     = (const float*)d_in[1];
    const float* bias  = (const float*)d_in[2];
    const float* gamma = (const float*)d_in[3];
    const float* beta  = (const float*)d_in[4];
    float* out = (float*)d_out;

    zero_stats_kernel<<<16, 256>>>();
    gemm_stats_kernel<<<dim3(BATCH / 128, 64), 128, SMEM_TOTAL>>>(x, w, bias);
    finalize_kernel<<<16, 256>>>(gamma, beta);
    pass2_kernel<<<(BATCH * OUT_DIM / 8) / 512, 256>>>(out);
}

// round 9
// speedup vs baseline: 1.5655x; 1.5655x over previous
#include <cuda_runtime.h>
#include <cuda_fp16.h>
#include <cstdint>

#define BATCH   4096
#define IN_DIM  4096
#define OUT_DIM 4096
#define BN_EPS  1e-3f

#define XS_STRIDE 68   // f32 words; ldmatrix phase conflict-free
#define BS_STRIDE 72   // f32 words; conflict-free B frags
#define ST_STRIDE 72   // halves

#define XS0_OFF   0
#define XS1_OFF   (128 * XS_STRIDE * 4)                 // 34816
#define BS_OFF    (2 * 128 * XS_STRIDE * 4)             // 69632
#define STAGE_OFF (BS_OFF + 64 * BS_STRIDE * 4)         // 88064
#define BIAS_OFF  (STAGE_OFF + 128 * ST_STRIDE * 2)     // 106496
#define SMEM_TOTAL (BIAS_OFF + 64 * 4)                  // 106752

#define NTILE 8        // row tiles per CTA (grid.x = 4)

// ---------------- scratch ---------------------------------------------------
__device__ float g_sum[OUT_DIM];
__device__ float g_sumsq[OUT_DIM];
__device__ float g_scale[OUT_DIM];
__device__ float g_shift[OUT_DIM];
__device__ uint2 g_mid[BATCH * OUT_DIM / 4];   // fp16 pre-BN intermediate (33MB)

__device__ __forceinline__ uint32_t smem_u32(const void* p) {
    uint32_t a;
    asm("{ .reg .u64 t; cvta.to.shared.u64 t, %1; cvt.u32.u64 %0, t; }" : "=r"(a) : "l"(p));
    return a;
}
__device__ __forceinline__ uint32_t f2tf32(float f) {
    uint32_t r;
    asm("cvt.rna.tf32.f32 %0, %1;" : "=r"(r) : "f"(f));
    return r;
}
__device__ __forceinline__ void cp_async16(uint32_t dst, const void* src) {
    asm volatile("cp.async.cg.shared.global [%0], [%1], 16;" :: "r"(dst), "l"(src));
}
__device__ __forceinline__ void ldsm_x4(uint32_t a[4], uint32_t addr) {
    asm volatile("ldmatrix.sync.aligned.m8n8.x4.shared.b16 {%0,%1,%2,%3}, [%4];"
                 : "=r"(a[0]), "=r"(a[1]), "=r"(a[2]), "=r"(a[3]) : "r"(addr));
}
__device__ __forceinline__ void mma_tf32(float c[4], const uint32_t a[4],
                                         const uint32_t b[2]) {
    asm volatile(
        "mma.sync.aligned.m16n8k8.row.col.f32.tf32.tf32.f32 "
        "{%0,%1,%2,%3}, {%4,%5,%6,%7}, {%8,%9}, {%0,%1,%2,%3};"
        : "+f"(c[0]), "+f"(c[1]), "+f"(c[2]), "+f"(c[3])
        : "r"(a[0]), "r"(a[1]), "r"(a[2]), "r"(a[3]), "r"(b[0]), "r"(b[1]));
}

// ---------------- kernels ---------------------------------------------------
__global__ void zero_stats_kernel() {
    int i = blockIdx.x * blockDim.x + threadIdx.x;
    if (i < OUT_DIM) { g_sum[i] = 0.f; g_sumsq[i] = 0.f; }
}

__device__ __forceinline__ void prefetch_tile(
    const float* __restrict__ x, uint32_t smem_base, uint32_t buf_off,
    int rowBase, int s, int tid)
{
    #pragma unroll
    for (int i = 0; i < 16; i++) {
        int idx = i * 128 + tid;
        int row = idx >> 4;
        int c4  = idx & 15;
        cp_async16(smem_base + buf_off + (row * XS_STRIDE + c4 * 4) * 4,
                   x + (size_t)(rowBase + row) * IN_DIM + s * 64 + c4 * 4);
    }
    asm volatile("cp.async.commit_group;" ::: "memory");
}

__global__ __launch_bounds__(128) void gemm_stats_kernel(
    const float* __restrict__ x, const float* __restrict__ w,
    const float* __restrict__ bias)
{
    extern __shared__ char smem[];
    const uint32_t smem_base = smem_u32(smem);
    uint32_t* Bs = (uint32_t*)(smem + BS_OFF);
    __half* stage = (__half*)(smem + STAGE_OFF);
    float* bias_s = (float*)(smem + BIAS_OFF);

    const int tid  = threadIdx.x;
    const int wid  = tid >> 5;
    const int lane = tid & 31;
    const int gid  = lane >> 2;
    const int tig  = lane & 3;
    const int s  = blockIdx.y;     // split
    const int bx = blockIdx.x;     // 0..3; tiles rt = bx + 4*t

    // prefetch tile 0
    prefetch_tile(x, smem_base, XS0_OFF, (bx + 0) * 128, s, tid);

    // ---- W block (LDG + exact tf32 rounding + STS), overlaps prefetch ----
    #pragma unroll
    for (int i = 0; i < 8; i++) {
        int idx = i * 128 + tid;
        int k  = idx >> 4;
        int c4 = idx & 15;
        float4 v = *(const float4*)(w + (size_t)(s * 64 + k) * OUT_DIM + s * 64 + c4 * 4);
        uint32_t* d = Bs + k * BS_STRIDE + c4 * 4;
        d[0] = f2tf32(v.x); d[1] = f2tf32(v.y); d[2] = f2tf32(v.z); d[3] = f2tf32(v.w);
    }
    if (tid < 16) {
        float4 v = *(const float4*)(bias + s * 64 + tid * 4);
        *(float4*)(bias_s + tid * 4) = v;
    }

    // ---- per-lane ldmatrix offsets (within an X buffer) ----
    const int quad = lane >> 3;
    const int lr   = lane & 7;
    uint32_t a_off[2];
    #pragma unroll
    for (int mc = 0; mc < 2; mc++) {
        int r  = wid * 32 + mc * 16 + (quad & 1) * 8 + lr;
        int cw = (quad >> 1) * 4;
        a_off[mc] = (r * XS_STRIDE + cw) * 4;
    }

    for (int t = 0; t < NTILE; t++) {
        const uint32_t cur_off = (t & 1) ? XS1_OFF : XS0_OFF;
        const int rowBase = (bx + 4 * t) * 128;
        if (t < NTILE - 1)
            prefetch_tile(x, smem_base, (t & 1) ? XS0_OFF : XS1_OFF,
                          (bx + 4 * (t + 1)) * 128, s, tid);
        if (t < NTILE - 1)
            asm volatile("cp.async.wait_group 1;" ::: "memory");
        else
            asm volatile("cp.async.wait_group 0;" ::: "memory");
        __syncthreads();   // (A) tile t visible; prev stats reads done

        // ---- tensor-core mainloop ----
        float c[2][8][4];
        #pragma unroll
        for (int mc = 0; mc < 2; mc++)
            #pragma unroll
            for (int nc = 0; nc < 8; nc++)
                #pragma unroll
                for (int q = 0; q < 4; q++)
                    c[mc][nc][q] = 0.f;

        #pragma unroll
        for (int kc = 0; kc < 8; kc++) {
            const int k0 = kc * 8;
            uint32_t a[2][4];
            ldsm_x4(a[0], smem_base + cur_off + a_off[0] + k0 * 4);
            ldsm_x4(a[1], smem_base + cur_off + a_off[1] + k0 * 4);
            uint32_t b[8][2];
            #pragma unroll
            for (int nc = 0; nc < 8; nc++) {
                b[nc][0] = Bs[(k0 + tig) * BS_STRIDE + nc * 8 + gid];
                b[nc][1] = Bs[(k0 + tig + 4) * BS_STRIDE + nc * 8 + gid];
            }
            #pragma unroll
            for (int mc = 0; mc < 2; mc++)
                #pragma unroll
                for (int nc = 0; nc < 8; nc++)
                    mma_tf32(c[mc][nc], a[mc], b[nc]);
        }

        // ---- bias add + fp16 stage (half2 writes, conflict-free) ----
        #pragma unroll
        for (int nc = 0; nc < 8; nc++) {
            const int col = nc * 8 + 2 * tig;
            const float bx_ = bias_s[col], by_ = bias_s[col + 1];
            #pragma unroll
            for (int mc = 0; mc < 2; mc++) {
                const int r = wid * 32 + mc * 16 + gid;
                __half2 h0 = __floats2half2_rn(c[mc][nc][0] + bx_, c[mc][nc][1] + by_);
                __half2 h1 = __floats2half2_rn(c[mc][nc][2] + bx_, c[mc][nc][3] + by_);
                *(__half2*)(stage + r * ST_STRIDE + col)       = h0;
                *(__half2*)(stage + (r + 8) * ST_STRIDE + col) = h1;
            }
        }
        __syncthreads();   // (C) stage complete

        // ---- coalesced uint2 stores to g_mid (R7 layout) ----
        #pragma unroll
        for (int i = 0; i < 16; i++) {
            int idx = i * 128 + tid;
            int row = idx >> 4;
            int c4  = idx & 15;
            uint2 u = *(uint2*)(stage + row * ST_STRIDE + c4 * 4);
            g_mid[((size_t)(rowBase + row) * OUT_DIM + s * 64 + c4 * 4) >> 2] = u;
        }
        // ---- per-column partial stats from fp16 stage ----
        {
            const int j = tid & 63;
            const int half = tid >> 6;
            float sm = 0.f, sq = 0.f;
            #pragma unroll 8
            for (int rr = 0; rr < 64; rr++) {
                float v = __half2float(stage[(half * 64 + rr) * ST_STRIDE + j]);
                sm += v;
                sq = fmaf(v, v, sq);
            }
            atomicAdd(&g_sum[s * 64 + j], sm);
            atomicAdd(&g_sumsq[s * 64 + j], sq);
        }
    }
}

__global__ void finalize_kernel(const float* __restrict__ gamma,
                                const float* __restrict__ beta) {
    int j = blockIdx.x * blockDim.x + threadIdx.x;
    if (j < OUT_DIM) {
        const float invB = 1.0f / (float)BATCH;
        float mean = g_sum[j] * invB;
        float var  = fmaxf(g_sumsq[j] * invB - mean * mean, 0.f);
        float sc   = gamma[j] * rsqrtf(var + BN_EPS);
        g_scale[j] = sc;
        g_shift[j] = fmaf(-mean, sc, beta[j]);
    }
}

__global__ __launch_bounds__(256) void pass2_kernel(float* __restrict__ out) {
    int base = blockIdx.x * 512 + threadIdx.x;
    #pragma unroll
    for (int t = 0; t < 2; t++) {
        int idx = base + t * 256;        // float4 index
        int j4  = idx & (OUT_DIM / 4 - 1);
        uint2 u = g_mid[idx];
        float2 f0 = __half22float2(*(__half2*)&u.x);
        float2 f1 = __half22float2(*(__half2*)&u.y);
        float4 sc = ((const float4*)g_scale)[j4];
        float4 sh = ((const float4*)g_shift)[j4];
        float4 v;
        v.x = fmaxf(fmaf(f0.x, sc.x, sh.x), 0.f);
        v.y = fmaxf(fmaf(f0.y, sc.y, sh.y), 0.f);
        v.z = fmaxf(fmaf(f1.x, sc.z, sh.z), 0.f);
        v.w = fmaxf(fmaf(f1.y, sc.w, sh.w), 0.f);
        ((float4*)out)[idx] = v;
    }
}

extern "C" void kernel_launch(void* const* d_in, const int* in_sizes, int n_in,
                              void* d_out, int out_size) {
    const float* x     = (const float*)d_in[0];
    const float* w     = (const float*)d_in[1];
    const float* bias  = (const float*)d_in[2];
    const float* gamma = (const float*)d_in[3];
    const float* beta  = (const float*)d_in[4];
    float* out = (float*)d_out;

    static bool attr_set = false;
    if (!attr_set) {
        cudaFuncSetAttribute(gemm_stats_kernel,
                             cudaFuncAttributeMaxDynamicSharedMemorySize, SMEM_TOTAL);
        attr_set = true;
    }

    zero_stats_kernel<<<16, 256>>>();
    gemm_stats_kernel<<<dim3(4, 64), 128, SMEM_TOTAL>>>(x, w, bias);
    finalize_kernel<<<16, 256>>>(gamma, beta);
    pass2_kernel<<<(BATCH * OUT_DIM / 4) / 512, 256>>>(out);
}

// round 10
// speedup vs baseline: 1.6458x; 1.0513x over previous
#include <cuda_runtime.h>
#include <cuda_fp16.h>
#include <cstdint>

#define BATCH   4096
#define IN_DIM  4096
#define OUT_DIM 4096
#define BN_EPS  1e-3f

#define XS_STRIDE 68   // f32 words; ldmatrix phase conflict-free
#define BS_STRIDE 72   // f32 words (temp B, lives in stage region)
#define ST_STRIDE 72   // halves
#define BF_STRIDE 20   // words per (kc,lane) row -> conflict-free LDS.128

#define XS0_OFF   0
#define XS1_OFF   (128 * XS_STRIDE * 4)                 // 34816
#define BF_OFF    (2 * 128 * XS_STRIDE * 4)             // 69632 (8*32*20*4 = 20480)
#define STAGE_OFF (BF_OFF + 20480)                      // 90112 (18432 B; also B temp)
#define BIAS_OFF  (STAGE_OFF + 128 * ST_STRIDE * 2)     // 108544
#define SMEM_TOTAL (BIAS_OFF + 64 * 4)                  // 108800

#define NTILE 8        // row tiles per CTA (grid.x = 4)

// ---------------- scratch ---------------------------------------------------
__device__ float g_sum[OUT_DIM];
__device__ float g_sumsq[OUT_DIM];
__device__ float g_scale[OUT_DIM];
__device__ float g_shift[OUT_DIM];
__device__ uint2 g_mid[BATCH * OUT_DIM / 4];   // fp16 pre-BN intermediate (33MB)

__device__ __forceinline__ uint32_t smem_u32(const void* p) {
    uint32_t a;
    asm("{ .reg .u64 t; cvta.to.shared.u64 t, %1; cvt.u32.u64 %0, t; }" : "=r"(a) : "l"(p));
    return a;
}
__device__ __forceinline__ uint32_t f2tf32(float f) {
    uint32_t r;
    asm("cvt.rna.tf32.f32 %0, %1;" : "=r"(r) : "f"(f));
    return r;
}
__device__ __forceinline__ void cp_async16(uint32_t dst, const void* src) {
    asm volatile("cp.async.cg.shared.global [%0], [%1], 16;" :: "r"(dst), "l"(src));
}
__device__ __forceinline__ void ldsm_x4(uint32_t a[4], uint32_t addr) {
    asm volatile("ldmatrix.sync.aligned.m8n8.x4.shared.b16 {%0,%1,%2,%3}, [%4];"
                 : "=r"(a[0]), "=r"(a[1]), "=r"(a[2]), "=r"(a[3]) : "r"(addr));
}
__device__ __forceinline__ void mma_tf32(float c[4], const uint32_t a[4],
                                         const uint32_t b0, const uint32_t b1) {
    asm volatile(
        "mma.sync.aligned.m16n8k8.row.col.f32.tf32.tf32.f32 "
        "{%0,%1,%2,%3}, {%4,%5,%6,%7}, {%8,%9}, {%0,%1,%2,%3};"
        : "+f"(c[0]), "+f"(c[1]), "+f"(c[2]), "+f"(c[3])
        : "r"(a[0]), "r"(a[1]), "r"(a[2]), "r"(a[3]), "r"(b0), "r"(b1));
}

// ---------------- kernels ---------------------------------------------------
__global__ void zero_stats_kernel() {
    int i = blockIdx.x * blockDim.x + threadIdx.x;
    if (i < OUT_DIM) { g_sum[i] = 0.f; g_sumsq[i] = 0.f; }
}

__device__ __forceinline__ void prefetch_tile(
    const float* __restrict__ x, uint32_t smem_base, uint32_t buf_off,
    int rowBase, int s, int tid)
{
    #pragma unroll
    for (int i = 0; i < 16; i++) {
        int idx = i * 128 + tid;
        int row = idx >> 4;
        int c4  = idx & 15;
        cp_async16(smem_base + buf_off + (row * XS_STRIDE + c4 * 4) * 4,
                   x + (size_t)(rowBase + row) * IN_DIM + s * 64 + c4 * 4);
    }
    asm volatile("cp.async.commit_group;" ::: "memory");
}

__global__ __launch_bounds__(128) void gemm_stats_kernel(
    const float* __restrict__ x, const float* __restrict__ w,
    const float* __restrict__ bias)
{
    extern __shared__ char smem[];
    const uint32_t smem_base = smem_u32(smem);
    uint32_t* BsT = (uint32_t*)(smem + STAGE_OFF);   // temp B (dies before stage use)
    __half* stage = (__half*)(smem + STAGE_OFF);
    float* bias_s = (float*)(smem + BIAS_OFF);

    const int tid  = threadIdx.x;
    const int wid  = tid >> 5;
    const int lane = tid & 31;
    const int gid  = lane >> 2;
    const int tig  = lane & 3;
    const int s  = blockIdx.y;     // split
    const int bx = blockIdx.x;     // 0..3; tiles rt = bx + 4*t

    // prefetch tile 0
    prefetch_tile(x, smem_base, XS0_OFF, (bx + 0) * 128, s, tid);

    // ---- W block (LDG + exact tf32 rounding) into temp K-major Bs ----
    #pragma unroll
    for (int i = 0; i < 8; i++) {
        int idx = i * 128 + tid;
        int k  = idx >> 4;
        int c4 = idx & 15;
        float4 v = *(const float4*)(w + (size_t)(s * 64 + k) * OUT_DIM + s * 64 + c4 * 4);
        uint32_t* d = BsT + k * BS_STRIDE + c4 * 4;
        d[0] = f2tf32(v.x); d[1] = f2tf32(v.y); d[2] = f2tf32(v.z); d[3] = f2tf32(v.w);
    }
    if (tid < 16) {
        float4 v = *(const float4*)(bias + s * 64 + tid * 4);
        *(float4*)(bias_s + tid * 4) = v;
    }
    __syncthreads();   // BsT visible

    // ---- build pre-swizzled B fragments Bf[kc][lane][16] (stride 20 words) ----
    #pragma unroll
    for (int it = 0; it < 2; it++) {
        const int kc = wid + 4 * it;
        const int k0 = kc * 8;
        uint32_t vals[16];
        #pragma unroll
        for (int nc = 0; nc < 8; nc++) {
            vals[2 * nc]     = BsT[(k0 + tig) * BS_STRIDE + nc * 8 + gid];
            vals[2 * nc + 1] = BsT[(k0 + tig + 4) * BS_STRIDE + nc * 8 + gid];
        }
        uint32_t dst = smem_base + BF_OFF + (kc * 32 + lane) * (BF_STRIDE * 4);
        #pragma unroll
        for (int j = 0; j < 4; j++)
            *(uint4*)(smem + (dst - smem_base) + j * 16) = *(uint4*)&vals[j * 4];
    }

    // ---- per-lane ldmatrix offsets (within an X buffer) ----
    const int quad = lane >> 3;
    const int lr   = lane & 7;
    uint32_t a_off[2];
    #pragma unroll
    for (int mc = 0; mc < 2; mc++) {
        int r  = wid * 32 + mc * 16 + (quad & 1) * 8 + lr;
        int cw = (quad >> 1) * 4;
        a_off[mc] = (r * XS_STRIDE + cw) * 4;
    }
    const uint32_t bf_lane = smem_base + BF_OFF + lane * (BF_STRIDE * 4);

    // ---- cross-tile register stats ----
    float st[8][4];
    #pragma unroll
    for (int nc = 0; nc < 8; nc++)
        #pragma unroll
        for (int q = 0; q < 4; q++)
            st[nc][q] = 0.f;

    for (int t = 0; t < NTILE; t++) {
        const uint32_t cur_off = (t & 1) ? XS1_OFF : XS0_OFF;
        const int rowBase = (bx + 4 * t) * 128;
        if (t < NTILE - 1) {
            prefetch_tile(x, smem_base, (t & 1) ? XS0_OFF : XS1_OFF,
                          (bx + 4 * (t + 1)) * 128, s, tid);
            asm volatile("cp.async.wait_group 1;" ::: "memory");
        } else {
            asm volatile("cp.async.wait_group 0;" ::: "memory");
        }
        __syncthreads();   // tile t visible; Bf built (t=0); prev stage stores done

        // ---- tensor-core mainloop ----
        float c[2][8][4];
        #pragma unroll
        for (int mc = 0; mc < 2; mc++)
            #pragma unroll
            for (int nc = 0; nc < 8; nc++)
                #pragma unroll
                for (int q = 0; q < 4; q++)
                    c[mc][nc][q] = 0.f;

        #pragma unroll
        for (int kc = 0; kc < 8; kc++) {
            uint32_t a[2][4];
            ldsm_x4(a[0], smem_base + cur_off + a_off[0] + kc * 32);
            ldsm_x4(a[1], smem_base + cur_off + a_off[1] + kc * 32);
            uint32_t b[16];
            #pragma unroll
            for (int j = 0; j < 4; j++)
                *(uint4*)&b[j * 4] = *(const uint4*)(smem + BF_OFF
                    + (kc * 32 + lane) * (BF_STRIDE * 4) + j * 16);
            #pragma unroll
            for (int mc = 0; mc < 2; mc++)
                #pragma unroll
                for (int nc = 0; nc < 8; nc++)
                    mma_tf32(c[mc][nc], a[mc], b[2 * nc], b[2 * nc + 1]);
        }
        __syncthreads();   // done reading stage-region? (stage==BsT only t=0: Bf build done pre-loop) / prev g_mid reads done

        // ---- bias add, stats accumulate, fp16 stage ----
        #pragma unroll
        for (int nc = 0; nc < 8; nc++) {
            const int col = nc * 8 + 2 * tig;
            const float bx_ = bias_s[col], by_ = bias_s[col + 1];
            #pragma unroll
            for (int mc = 0; mc < 2; mc++) {
                const int r = wid * 32 + mc * 16 + gid;
                float v00 = c[mc][nc][0] + bx_;
                float v01 = c[mc][nc][1] + by_;
                float v10 = c[mc][nc][2] + bx_;
                float v11 = c[mc][nc][3] + by_;
                st[nc][0] += v00 + v10;
                st[nc][1] += v01 + v11;
                st[nc][2] += fmaf(v00, v00, v10 * v10);
                st[nc][3] += fmaf(v01, v01, v11 * v11);
                __half2 h0 = __floats2half2_rn(v00, v01);
                __half2 h1 = __floats2half2_rn(v10, v11);
                *(__half2*)(stage + r * ST_STRIDE + col)       = h0;
                *(__half2*)(stage + (r + 8) * ST_STRIDE + col) = h1;
            }
        }
        __syncthreads();   // stage complete

        // ---- coalesced uint2 stores to g_mid ----
        #pragma unroll
        for (int i = 0; i < 16; i++) {
            int idx = i * 128 + tid;
            int row = idx >> 4;
            int c4  = idx & 15;
            uint2 u = *(uint2*)(stage + row * ST_STRIDE + c4 * 4);
            g_mid[((size_t)(rowBase + row) * OUT_DIM + s * 64 + c4 * 4) >> 2] = u;
        }
    }

    // ---- final stats reduce: shuffle across gid, one atomic per col ----
    const int colBase = s * 64;
    #pragma unroll
    for (int nc = 0; nc < 8; nc++) {
        float s0 = st[nc][0], s1 = st[nc][1], q0 = st[nc][2], q1 = st[nc][3];
        #pragma unroll
        for (int m = 4; m < 32; m <<= 1) {
            s0 += __shfl_xor_sync(0xffffffffu, s0, m);
            s1 += __shfl_xor_sync(0xffffffffu, s1, m);
            q0 += __shfl_xor_sync(0xffffffffu, q0, m);
            q1 += __shfl_xor_sync(0xffffffffu, q1, m);
        }
        if (gid == 0) {
            const int col = colBase + nc * 8 + 2 * tig;
            atomicAdd(&g_sum[col],       s0);
            atomicAdd(&g_sum[col + 1],   s1);
            atomicAdd(&g_sumsq[col],     q0);
            atomicAdd(&g_sumsq[col + 1], q1);
        }
    }
}

__global__ void finalize_kernel(const float* __restrict__ gamma,
                                const float* __restrict__ beta) {
    int j = blockIdx.x * blockDim.x + threadIdx.x;
    if (j < OUT_DIM) {
        const float invB = 1.0f / (float)BATCH;
        float mean = g_sum[j] * invB;
        float var  = fmaxf(g_sumsq[j] * invB - mean * mean, 0.f);
        float sc   = gamma[j] * rsqrtf(var + BN_EPS);
        g_scale[j] = sc;
        g_shift[j] = fmaf(-mean, sc, beta[j]);
    }
}

__global__ __launch_bounds__(256) void pass2_kernel(float* __restrict__ out) {
    int base = blockIdx.x * 512 + threadIdx.x;
    #pragma unroll
    for (int t = 0; t < 2; t++) {
        int idx = base + t * 256;        // float4 index
        int j4  = idx & (OUT_DIM / 4 - 1);
        uint2 u = g_mid[idx];
        float2 f0 = __half22float2(*(__half2*)&u.x);
        float2 f1 = __half22float2(*(__half2*)&u.y);
        float4 sc = ((const float4*)g_scale)[j4];
        float4 sh = ((const float4*)g_shift)[j4];
        float4 v;
        v.x = fmaxf(fmaf(f0.x, sc.x, sh.x), 0.f);
        v.y = fmaxf(fmaf(f0.y, sc.y, sh.y), 0.f);
        v.z = fmaxf(fmaf(f1.x, sc.z, sh.z), 0.f);
        v.w = fmaxf(fmaf(f1.y, sc.w, sh.w), 0.f);
        ((float4*)out)[idx] = v;
    }
}

extern "C" void kernel_launch(void* const* d_in, const int* in_sizes, int n_in,
                              void* d_out, int out_size) {
    const float* x     = (const float*)d_in[0];
    const float* w     = (const float*)d_in[1];
    const float* bias  = (const float*)d_in[2];
    const float* gamma = (const float*)d_in[3];
    const float* beta  = (const float*)d_in[4];
    float* out = (float*)d_out;

    static bool attr_set = false;
    if (!attr_set) {
        cudaFuncSetAttribute(gemm_stats_kernel,
                             cudaFuncAttributeMaxDynamicSharedMemorySize, SMEM_TOTAL);
        attr_set = true;
    }

    zero_stats_kernel<<<16, 256>>>();
    gemm_stats_kernel<<<dim3(4, 64), 128, SMEM_TOTAL>>>(x, w, bias);
    finalize_kernel<<<16, 256>>>(gamma, beta);
    pass2_kernel<<<(BATCH * OUT_DIM / 4) / 512, 256>>>(out);
}